// round 13
// baseline (speedup 1.0000x reference)
#include <cuda_runtime.h>
#include <cuda_bf16.h>

// Problem constants
#define D_DIM   1024
#define D4      (D_DIM / 4)          // 256 float4 lanes
#define L_COMP  16384
#define L_FULL  32768
#define EPS_P   1e-4f

#define CHUNK_T 32                   // positions per chunk
#define NCHUNK  (L_COMP / CHUNK_T)   // 512 chunks -> entire grid resident (1 wave)

// Scratch (allocation-free rule: __device__ globals)
__device__ float  g_A[NCHUNK];               // per-chunk decay product (scalar)
__device__ float4 g_Z[NCHUNK * D4];          // chunk-local scan endpoints
__device__ int    g_flag[NCHUNK];            // 0 = not ready, 1 = Z/A published
__device__ int    g_pos[L_COMP + 1];         // boundary positions; [L_COMP] = L_FULL

__device__ __forceinline__ int ld_acquire(const int* p) {
    int v;
    asm volatile("ld.acquire.gpu.global.b32 %0, [%1];" : "=r"(v) : "l"(p));
    return v;
}
__device__ __forceinline__ void st_release(int* p, int v) {
    asm volatile("st.release.gpu.global.b32 [%0], %1;" :: "l"(p), "r"(v));
}

// ---------------------------------------------------------------------------
// prep: block 0 scans b -> pos via warp ballots (coalesced); block 1 zeroes
// flags (must happen EVERY launch so graph replays are deterministic)
// ---------------------------------------------------------------------------
__global__ void k_prep(const int* __restrict__ b) {
    int tid = threadIdx.x;
    if (blockIdx.x == 1) {
        if (tid < NCHUNK) g_flag[tid] = 0;
        return;
    }
    int w    = tid >> 5;
    int lane = tid & 31;
    int base = w * 1024;                 // warp-contiguous segment
    __shared__ int woff[32];

    // pass 1: per-warp one-count, coalesced loads (lane-adjacent addresses)
    int cnt = 0;
    #pragma unroll 8
    for (int i = 0; i < 32; i++) {
        int v = b[base + i * 32 + lane];
        unsigned m = __ballot_sync(0xffffffffu, v != 0);
        cnt += __popc(m);                // warp-uniform
    }
    if (lane == 0) woff[w] = cnt;
    __syncthreads();

    // warp 0: exclusive prefix over the 32 warp counts
    if (w == 0) {
        int orig = woff[lane];
        int incl = orig;
        #pragma unroll
        for (int off = 1; off < 32; off <<= 1) {
            int u = __shfl_up_sync(0xffffffffu, incl, off);
            if (lane >= off) incl += u;
        }
        woff[lane] = incl - orig;        // exclusive
    }
    __syncthreads();

    // pass 2: scatter positions (b re-read hits L1)
    int run = woff[w];
    #pragma unroll 8
    for (int i = 0; i < 32; i++) {
        int idx = base + i * 32 + lane;
        int v = b[idx];
        unsigned m = __ballot_sync(0xffffffffu, v != 0);
        if (v) g_pos[run + __popc(m & ((1u << lane) - 1u))] = idx;
        run += __popc(m);
    }
    if (tid == 0) g_pos[L_COMP] = L_FULL;
}

// ---------------------------------------------------------------------------
// fused single-pass scan with decoupled lookback + scatter-replicate epilogue
// grid = NCHUNK (512) blocks, 256 threads, thread owns 4 channels (float4).
// 512 CTAs at 4/SM (regs<=64) => whole grid resident in ONE wave: all x loads
// in flight concurrently, lookback flags produced while consumers are resident.
// ---------------------------------------------------------------------------
__global__ void __launch_bounds__(D4, 4) k_fused(const float4* __restrict__ x,
                                                 const float* __restrict__ ps,
                                                 float4* __restrict__ out) {
    int c  = blockIdx.x;
    int d4 = threadIdx.x;
    int t0 = c * CHUNK_T;

    __shared__ float sp[CHUNK_T];
    __shared__ int   spos[CHUNK_T + 1];
    __shared__ float s_a;

    if (d4 < CHUNK_T) {
        float p = ps[t0 + d4];
        sp[d4] = fminf(fmaxf(p, EPS_P), 1.0f - EPS_P);
    }
    if (d4 < CHUNK_T + 1) spos[d4] = g_pos[t0 + d4];
    __syncthreads();

    // ---- phase A: chunk-local scan (the only DRAM read of x) ----
    const float4* xp = x + (size_t)t0 * D4 + d4;
    float4 z = make_float4(0.f, 0.f, 0.f, 0.f);
    #pragma unroll 8
    for (int t = 0; t < CHUNK_T; t++) {
        float p = sp[t];
        float a = 1.0f - p;
        float4 xv = xp[(size_t)t * D4];
        z.x = fmaf(a, z.x, p * xv.x);
        z.y = fmaf(a, z.y, p * xv.y);
        z.z = fmaf(a, z.z, p * xv.z);
        z.w = fmaf(a, z.w, p * xv.w);
    }
    g_Z[(size_t)c * D4 + d4] = z;
    if (d4 == 0) {
        float prod = 1.0f;
        #pragma unroll
        for (int t = 0; t < CHUNK_T; t++) prod *= (1.0f - sp[t]);
        g_A[c] = prod;
    }
    __syncthreads();                 // all Z/A writes issued
    if (d4 == 0) {
        __threadfence();             // make them visible device-wide
        st_release(&g_flag[c], 1);
    }

    // ---- lookback: accumulate carry from predecessors ----
    // p~U(0,1) => A_chunk ~ e^-32 ~ 1e-14; amul underflows past significance
    // within ~3 predecessors -> early exit keeps lookback O(1).
    float4 carry = make_float4(0.f, 0.f, 0.f, 0.f);
    if (c > 0) {
        float amul = 1.0f;
        for (int j = c - 1; j >= 0; j--) {
            if (d4 == 0) {
                if (ld_acquire(&g_flag[j]) == 0) {
                    while (ld_acquire(&g_flag[j]) == 0) __nanosleep(40);
                }
                s_a = g_A[j];
            }
            __syncthreads();
            float aj = s_a;
            float4 zj = g_Z[(size_t)j * D4 + d4];
            carry.x = fmaf(amul, zj.x, carry.x);
            carry.y = fmaf(amul, zj.y, carry.y);
            carry.z = fmaf(amul, zj.z, carry.z);
            carry.w = fmaf(amul, zj.w, carry.w);
            amul *= aj;              // uniform across the block
            __syncthreads();         // protect s_a before next iteration
            if (amul < 1e-35f) break;
        }
    }

    // ---- phase B: re-scan from carry, scatter-replicate to out ----
    // x re-read hits L1/L2 (x fits in L2; slice just touched in phase A).
    float4 zz = carry;
    int seg_s = spos[0];
    #pragma unroll 4
    for (int t = 0; t < CHUNK_T; t++) {
        float p = sp[t];
        float a = 1.0f - p;
        float4 xv = xp[(size_t)t * D4];
        zz.x = fmaf(a, zz.x, p * xv.x);
        zz.y = fmaf(a, zz.y, p * xv.y);
        zz.z = fmaf(a, zz.z, p * xv.z);
        zz.w = fmaf(a, zz.w, p * xv.w);
        int seg_e = spos[t + 1];                 // warp-uniform
        for (int tf = seg_s; tf < seg_e; tf++) { // warp-uniform trip count
            __stcs(out + (size_t)tf * D4 + d4, zz);  // write-once: evict-first
        }
        seg_s = seg_e;
    }
}

// ---------------------------------------------------------------------------
extern "C" void kernel_launch(void* const* d_in, const int* in_sizes, int n_in,
                              void* d_out, int out_size) {
    const float* x  = (const float*)d_in[0];   // (1, 16384, 1024) f32
    const float* ps = (const float*)d_in[1];   // (16384,) f32
    const int*   b  = (const int*)d_in[2];     // (1, 32768) i32
    float4* out = (float4*)d_out;              // (1, 32768, 1024) f32

    k_prep<<<2, 1024>>>(b);
    k_fused<<<NCHUNK, D4>>>((const float4*)x, ps, out);
}